// round 15
// baseline (speedup 1.0000x reference)
#include <cuda_runtime.h>
#include <cuda_fp16.h>
#include <cstdint>

// ---------------------------------------------------------------------------
// out[8192,4096] = x[8192,4096] @ W^T + bias
//   W = (W_q - zeros) * scales * scale2 * mask   (static per launch)
//
// Classic tensor-core path (base PTX on this toolchain):
// mma.sync.m16n8k16 (HMMA) + cp.async (LDGSTS) + ldmatrix (LDSM).
// R15 = R14 GEMM (256x128x64 CTA tile, 8 warps 4m x 2n, 64x64 warp tiles,
// reg double-buffered frags, 4-stage cp.async, 1 CTA/SM) + prep with
// IN-BLOCK mask-mode detection: every dequant block scans the same fixed
// 2048-word mask prefix (deterministic, identical result) -> the separate
// detect launch and its serialization gap are eliminated. 2-launch graph.
// ---------------------------------------------------------------------------

#define TOKS 8192
#define INF  4096
#define OUTF 4096

__device__ __align__(256) __half g_Xh[(size_t)TOKS * INF];   // 64 MB A (row-major, K contig)
__device__ __align__(256) __half g_Wh[(size_t)OUTF * INF];   // 32 MB B ([n][k], K contig)

static constexpr int CONV_BLOCKS = 16384;   // x convert: 16384*256 threads x 8 elems
static constexpr int DEQ_BLOCKS  = 8192;    // W dequant:  8192*256 threads x 8 elems

// Fused prep: blocks [0, CONV_BLOCKS) convert x -> g_Xh (fp16);
//             blocks [CONV_BLOCKS, CONV_BLOCKS+DEQ_BLOCKS) dequant W -> g_Wh,
//             with per-block mask-mode detection (same fixed prefix scan).
__global__ void prep_kernel(const float4* __restrict__ x,
                            const int* __restrict__ Wq, const float* __restrict__ scales,
                            const float* __restrict__ zeros, const void* __restrict__ mask,
                            const float* __restrict__ scale2) {
    if (blockIdx.x < CONV_BLOCKS) {
        // ---- convert x (identical body to proven convert_x_kernel) ----
        size_t i = (size_t)blockIdx.x * blockDim.x + threadIdx.x;
        float4 a = x[i * 2 + 0];
        float4 b = x[i * 2 + 1];
        unsigned short h[8];
        h[0] = __half_as_ushort(__float2half_rn(a.x)); h[1] = __half_as_ushort(__float2half_rn(a.y));
        h[2] = __half_as_ushort(__float2half_rn(a.z)); h[3] = __half_as_ushort(__float2half_rn(a.w));
        h[4] = __half_as_ushort(__float2half_rn(b.x)); h[5] = __half_as_ushort(__float2half_rn(b.y));
        h[6] = __half_as_ushort(__float2half_rn(b.z)); h[7] = __half_as_ushort(__float2half_rn(b.w));
        uint4 v;
        v.x = (uint32_t)h[0] | ((uint32_t)h[1] << 16);
        v.y = (uint32_t)h[2] | ((uint32_t)h[3] << 16);
        v.z = (uint32_t)h[4] | ((uint32_t)h[5] << 16);
        v.w = (uint32_t)h[6] | ((uint32_t)h[7] << 16);
        ((uint4*)g_Xh)[i] = v;
    } else {
        // ---- in-block mask-mode detection (deterministic: every block scans
        //      the SAME fixed 2048-word prefix and OR-reduces; identical result
        //      in all blocks, no cross-block communication needed) ----
        __shared__ int s_f32, s_gt1;
        if (threadIdx.x == 0) { s_f32 = 0; s_gt1 = 0; }
        __syncthreads();
        {
            const unsigned int* mh = (const unsigned int*)mask;
            int f32 = 0, gt1 = 0;
#pragma unroll
            for (int i = 0; i < 8; i++) {
                unsigned v = mh[threadIdx.x * 8 + i];
                f32 |= (v == 0x3F800000u);
                gt1 |= (v > 1u);
            }
            if (f32) atomicOr(&s_f32, 1);
            if (gt1) atomicOr(&s_gt1, 1);
        }
        __syncthreads();
        const int mode = s_f32 ? 2 : (s_gt1 ? 0 : 1);   // 0=int8, 1=int32, 2=f32

        // ---- dequant W (identical body to proven dequant_w_kernel) ----
        size_t t = (size_t)(blockIdx.x - CONV_BLOCKS) * blockDim.x + threadIdx.x;
        size_t base = t * 8;
        int row = (int)(base >> 12);
        int col = (int)(base & 4095);
        float s = scales[row];
        float z = zeros[row];
        int4 q0 = *(const int4*)(Wq + base);
        int4 q1 = *(const int4*)(Wq + base + 4);
        float4 c0 = *(const float4*)(scale2 + col);
        float4 c1 = *(const float4*)(scale2 + col + 4);
        float mv[8];
        if (mode == 0) {
            uint2 mb = *(const uint2*)((const unsigned char*)mask + base);
            mv[0] = (mb.x & 0x000000FFu) ? 1.f : 0.f;
            mv[1] = (mb.x & 0x0000FF00u) ? 1.f : 0.f;
            mv[2] = (mb.x & 0x00FF0000u) ? 1.f : 0.f;
            mv[3] = (mb.x & 0xFF000000u) ? 1.f : 0.f;
            mv[4] = (mb.y & 0x000000FFu) ? 1.f : 0.f;
            mv[5] = (mb.y & 0x0000FF00u) ? 1.f : 0.f;
            mv[6] = (mb.y & 0x00FF0000u) ? 1.f : 0.f;
            mv[7] = (mb.y & 0xFF000000u) ? 1.f : 0.f;
        } else if (mode == 1) {
            int4 m0 = *(const int4*)((const int*)mask + base);
            int4 m1 = *(const int4*)((const int*)mask + base + 4);
            mv[0] = m0.x ? 1.f : 0.f; mv[1] = m0.y ? 1.f : 0.f;
            mv[2] = m0.z ? 1.f : 0.f; mv[3] = m0.w ? 1.f : 0.f;
            mv[4] = m1.x ? 1.f : 0.f; mv[5] = m1.y ? 1.f : 0.f;
            mv[6] = m1.z ? 1.f : 0.f; mv[7] = m1.w ? 1.f : 0.f;
        } else {
            float4 m0 = *(const float4*)((const float*)mask + base);
            float4 m1 = *(const float4*)((const float*)mask + base + 4);
            mv[0] = m0.x; mv[1] = m0.y; mv[2] = m0.z; mv[3] = m0.w;
            mv[4] = m1.x; mv[5] = m1.y; mv[6] = m1.z; mv[7] = m1.w;
        }
        float qf[8] = {(float)q0.x, (float)q0.y, (float)q0.z, (float)q0.w,
                       (float)q1.x, (float)q1.y, (float)q1.z, (float)q1.w};
        float cf[8] = {c0.x, c0.y, c0.z, c0.w, c1.x, c1.y, c1.z, c1.w};
        unsigned short h[8];
#pragma unroll
        for (int i = 0; i < 8; i++)
            h[i] = __half_as_ushort(__float2half_rn((qf[i] - z) * s * cf[i] * mv[i]));
        uint4 v;
        v.x = (uint32_t)h[0] | ((uint32_t)h[1] << 16);
        v.y = (uint32_t)h[2] | ((uint32_t)h[3] << 16);
        v.z = (uint32_t)h[4] | ((uint32_t)h[5] << 16);
        v.w = (uint32_t)h[6] | ((uint32_t)h[7] << 16);
        *(uint4*)(g_Wh + base) = v;
    }
}

// ---------------------------------------------------------------------------
// GEMM: 256x128x64 block tile, 256 threads (8 warps, 4m x 2n), warp tile 64x64,
// register double-buffered fragments, 4-stage cp.async, 1 CTA/SM.
// smem rows: 64 halves padded to 72 (144 B) => conflict-free ldmatrix.
// ---------------------------------------------------------------------------
static constexpr int BM = 256, BN = 128, BK = 64, STAGES = 4;
static constexpr int KITER = INF / BK;                 // 64
static constexpr int ROWB = 144;                       // padded row bytes (72 halves)
static constexpr int A_BYTES = BM * ROWB;              // 36864
static constexpr int B_BYTES = BN * ROWB;              // 18432
static constexpr int STAGE_BYTES = A_BYTES + B_BYTES;  // 55296
static constexpr int SMEM_CTRL = 512;                  // bias tile (128 f32)
static constexpr int SMEM_TOTAL = SMEM_CTRL + STAGES * STAGE_BYTES;  // 221696

__device__ __forceinline__ uint32_t smem_u32(const void* p) {
    uint32_t a;
    asm("{ .reg .u64 t; cvta.to.shared.u64 t, %1; cvt.u32.u64 %0, t; }" : "=r"(a) : "l"(p));
    return a;
}

__device__ __forceinline__ void cp_async16(uint32_t sdst, const void* gsrc) {
    asm volatile("cp.async.cg.shared.global [%0], [%1], 16;" :: "r"(sdst), "l"(gsrc) : "memory");
}

__device__ __forceinline__ void ldmatrix_x4(uint32_t& r0, uint32_t& r1, uint32_t& r2, uint32_t& r3,
                                            uint32_t addr) {
    asm volatile("ldmatrix.sync.aligned.m8n8.x4.shared.b16 {%0,%1,%2,%3}, [%4];"
                 : "=r"(r0), "=r"(r1), "=r"(r2), "=r"(r3) : "r"(addr));
}

__device__ __forceinline__ void mma16816(float* c, uint32_t a0, uint32_t a1, uint32_t a2,
                                         uint32_t a3, uint32_t b0, uint32_t b1) {
    asm volatile(
        "mma.sync.aligned.m16n8k16.row.col.f32.f16.f16.f32 "
        "{%0,%1,%2,%3}, {%4,%5,%6,%7}, {%8,%9}, {%0,%1,%2,%3};"
        : "+f"(c[0]), "+f"(c[1]), "+f"(c[2]), "+f"(c[3])
        : "r"(a0), "r"(a1), "r"(a2), "r"(a3), "r"(b0), "r"(b1));
}

// full-burst stage load (R6 shape): A 256x8 chunks (8/thr), B 128x8 (4/thr)
__device__ __forceinline__ void load_stage(uint32_t sb, int buf, const __half* Ag, const __half* Bg,
                                           int k0, int tid) {
    uint32_t sA = sb + SMEM_CTRL + buf * STAGE_BYTES;
    uint32_t sB = sA + A_BYTES;
    const __half* Ak = Ag + k0;
    const __half* Bk = Bg + k0;
#pragma unroll
    for (int i = 0; i < 8; i++) {          // A: 256 rows x 8 16B-chunks = 2048 / 256 thr
        int ch = tid + (i << 8);
        int r = ch >> 3, c = ch & 7;
        cp_async16(sA + (uint32_t)r * ROWB + (uint32_t)(c << 4), Ak + (size_t)r * INF + (c << 3));
    }
#pragma unroll
    for (int i = 0; i < 4; i++) {          // B: 128 rows x 8 chunks = 1024 / 256 thr
        int ch = tid + (i << 8);
        int r = ch >> 3, c = ch & 7;
        cp_async16(sB + (uint32_t)r * ROWB + (uint32_t)(c << 4), Bk + (size_t)r * INF + (c << 3));
    }
}

// fragment prefetch: A 4 x4 (m64 x k16), B 4 x4 (n64 x k16)
__device__ __forceinline__ void ld_frags(uint32_t (&fa)[4][4], uint32_t (&fb)[4][4],
                                         uint32_t sA, uint32_t sB,
                                         uint32_t a_off, uint32_t b_off, uint32_t kb) {
#pragma unroll
    for (int mt = 0; mt < 4; mt++)
        ldmatrix_x4(fa[mt][0], fa[mt][1], fa[mt][2], fa[mt][3],
                    sA + a_off + (uint32_t)mt * 16 * ROWB + kb);
#pragma unroll
    for (int g = 0; g < 4; g++)
        ldmatrix_x4(fb[g][0], fb[g][1], fb[g][2], fb[g][3],
                    sB + b_off + (uint32_t)g * 16 * ROWB + kb);
}

__device__ __forceinline__ void compute_frags(float (&acc)[4][8][4],
                                              const uint32_t (&fa)[4][4],
                                              const uint32_t (&fb)[4][4]) {
#pragma unroll
    for (int mt = 0; mt < 4; mt++)
#pragma unroll
        for (int g = 0; g < 4; g++) {
            mma16816(acc[mt][g * 2 + 0], fa[mt][0], fa[mt][1], fa[mt][2], fa[mt][3],
                     fb[g][0], fb[g][1]);
            mma16816(acc[mt][g * 2 + 1], fa[mt][0], fa[mt][1], fa[mt][2], fa[mt][3],
                     fb[g][2], fb[g][3]);
        }
}

__global__ void __launch_bounds__(256, 1)
gemm_f16_kernel(const float* __restrict__ bias, float* __restrict__ out) {
    extern __shared__ char smem[];
    const uint32_t sb = smem_u32(smem);
    const int tid = threadIdx.x, wid = tid >> 5, lid = tid & 31;
    const int wm = wid & 3, wn = wid >> 2;           // warp grid 4m x 2n
    const int tile_n = blockIdx.x & 31;              // n-fast raster (B reuse in L2)
    const int tile_m = blockIdx.x >> 5;              // 32 m-tiles

    // stage bias tile (128 floats for this n-tile)
    if (tid < 128) ((float*)smem)[tid] = bias[tile_n * BN + tid];

    const __half* Ag = g_Xh + (size_t)tile_m * BM * INF;
    const __half* Bg = g_Wh + (size_t)tile_n * BN * INF;

    // ldmatrix per-lane base offsets (within a stage's tiles)
    const uint32_t a_off = (uint32_t)(wm * 64 + (lid & 15)) * ROWB + (uint32_t)(lid >> 4) * 16;
    const uint32_t b_off = (uint32_t)(wn * 64 + ((lid >> 4) << 3) + (lid & 7)) * ROWB
                         + (uint32_t)((lid >> 3) & 1) * 16;

    float acc[4][8][4];
#pragma unroll
    for (int mt = 0; mt < 4; mt++)
#pragma unroll
        for (int nt = 0; nt < 8; nt++)
#pragma unroll
            for (int j = 0; j < 4; j++) acc[mt][nt][j] = 0.f;

    // prologue: load stages 0,1,2
    load_stage(sb, 0, Ag, Bg, 0, tid);
    asm volatile("cp.async.commit_group;" ::: "memory");
    load_stage(sb, 1, Ag, Bg, BK, tid);
    asm volatile("cp.async.commit_group;" ::: "memory");
    load_stage(sb, 2, Ag, Bg, 2 * BK, tid);
    asm volatile("cp.async.commit_group;" ::: "memory");
    asm volatile("cp.async.wait_group 2;" ::: "memory");
    __syncthreads();

    uint32_t fa0[4][4], fb0[4][4], fa1[4][4], fb1[4][4];
    // preload step-0 fragments from stage 0
    ld_frags(fa0, fb0, sb + SMEM_CTRL, sb + SMEM_CTRL + A_BYTES, a_off, b_off, 0);

    int buf = 0;                 // stage buffer for iter s
    int lbuf = 3;                // stage buffer for iter s+3 loads
    for (int s = 0; s < KITER; s++) {
        const uint32_t sA = sb + SMEM_CTRL + buf * STAGE_BYTES;
        const uint32_t sBt = sA + A_BYTES;

        // step 0: prefetch frags k16#1; issue loads for stage s+3; compute k16#0
        ld_frags(fa1, fb1, sA, sBt, a_off, b_off, 32);
        int ns = s + STAGES - 1;
        if (ns < KITER) load_stage(sb, lbuf, Ag, Bg, ns * BK, tid);
        asm volatile("cp.async.commit_group;" ::: "memory");
        compute_frags(acc, fa0, fb0);

        // step 1: prefetch k16#2; compute k16#1
        ld_frags(fa0, fb0, sA, sBt, a_off, b_off, 64);
        compute_frags(acc, fa1, fb1);

        // step 2: prefetch k16#3; compute k16#2
        ld_frags(fa1, fb1, sA, sBt, a_off, b_off, 96);
        compute_frags(acc, fa0, fb0);

        // step 3: stage s+1 ready (2 groups may remain outstanding);
        //         prefetch its k16#0; compute k16#3
        asm volatile("cp.async.wait_group 2;" ::: "memory");
        __syncthreads();
        buf = (buf + 1) & 3;
        lbuf = (lbuf + 1) & 3;
        if (s + 1 < KITER) {
            const uint32_t nA = sb + SMEM_CTRL + buf * STAGE_BYTES;
            ld_frags(fa0, fb0, nA, nA + A_BYTES, a_off, b_off, 0);
        }
        compute_frags(acc, fa1, fb1);
    }

    // epilogue: fragment c -> global (+bias)
    const float* bsm = (const float*)smem;
    float* outbase = out + (size_t)(tile_m * BM + wm * 64) * OUTF + tile_n * BN;
    const int rl = lid >> 2;
    const int cl = (lid & 3) * 2;
#pragma unroll
    for (int mt = 0; mt < 4; mt++) {
#pragma unroll
        for (int nt = 0; nt < 8; nt++) {
            int c = wn * 64 + nt * 8 + cl;
            float b0v = bsm[c], b1v = bsm[c + 1];
            int r = mt * 16 + rl;
            float2 v0 = make_float2(acc[mt][nt][0] + b0v, acc[mt][nt][1] + b1v);
            *(float2*)(outbase + (size_t)r * OUTF + c) = v0;
            float2 v1 = make_float2(acc[mt][nt][2] + b0v, acc[mt][nt][3] + b1v);
            *(float2*)(outbase + (size_t)(r + 8) * OUTF + c) = v1;
        }
    }
}

// ---------------------------------------------------------------------------
extern "C" void kernel_launch(void* const* d_in, const int* in_sizes, int n_in,
                              void* d_out, int out_size) {
    const float* x      = (const float*)d_in[0];
    const int*   Wq     = (const int*)d_in[1];
    const float* scales = (const float*)d_in[2];
    const float* zeros  = (const float*)d_in[3];
    const void*  mask   = d_in[4];
    const float* scale2 = (const float*)d_in[5];
    const float* bias   = (const float*)d_in[6];
    float*       out    = (float*)d_out;

    cudaFuncSetAttribute(gemm_f16_kernel, cudaFuncAttributeMaxDynamicSharedMemorySize, SMEM_TOTAL);

    prep_kernel<<<CONV_BLOCKS + DEQ_BLOCKS, 256>>>((const float4*)x, Wq, scales, zeros,
                                                   mask, scale2);
    gemm_f16_kernel<<<(TOKS / BM) * (OUTF / BN), 256, SMEM_TOTAL>>>(bias, out);
}

// round 16
// speedup vs baseline: 1.0016x; 1.0016x over previous
#include <cuda_runtime.h>
#include <cuda_fp16.h>
#include <cstdint>

// ---------------------------------------------------------------------------
// out[8192,4096] = x[8192,4096] @ W^T + bias
//   W = (W_q - zeros) * scales * scale2 * mask   (static per launch)
//
// Classic tensor-core path (base PTX on this toolchain):
// mma.sync.m16n8k16 (HMMA) + cp.async (LDGSTS) + ldmatrix (LDSM).
// FINAL (== R14, best measured): detect_mask + fused prep (convert_x ++
// dequant_w in one kernel) + GEMM with 256x128x64 CTA tile, 8 warps (4m x 2n),
// 64x64 warp tiles, register double-buffered fragments, 4-stage cp.async,
// 1 CTA/SM. GEMM converged at ~85.5% tensor-pipe (531 us vs 453 us ideal);
// aux at bandwidth+launch floor.
// ---------------------------------------------------------------------------

#define TOKS 8192
#define INF  4096
#define OUTF 4096

__device__ __align__(256) __half g_Xh[(size_t)TOKS * INF];   // 64 MB A (row-major, K contig)
__device__ __align__(256) __half g_Wh[(size_t)OUTF * INF];   // 32 MB B ([n][k], K contig)
__device__ int g_mask_mode;   // 0 = int8, 1 = int32, 2 = float32

// ---------------------------------------------------------------------------
// Aux kernels
// ---------------------------------------------------------------------------
__global__ void detect_mask_kernel(const unsigned int* __restrict__ m) {
    __shared__ int s_f32, s_gt1;
    if (threadIdx.x == 0) { s_f32 = 0; s_gt1 = 0; }
    __syncthreads();
    int f32 = 0, gt1 = 0;
#pragma unroll
    for (int i = 0; i < 8; i++) {
        unsigned v = m[threadIdx.x * 8 + i];
        f32 |= (v == 0x3F800000u);
        gt1 |= (v > 1u);
    }
    if (f32) atomicOr(&s_f32, 1);
    if (gt1) atomicOr(&s_gt1, 1);
    __syncthreads();
    if (threadIdx.x == 0)
        g_mask_mode = s_f32 ? 2 : (s_gt1 ? 0 : 1);
}

static constexpr int CONV_BLOCKS = 16384;   // x convert: 16384*256 threads x 8 elems
static constexpr int DEQ_BLOCKS  = 8192;    // W dequant:  8192*256 threads x 8 elems

// Fused prep: blocks [0, CONV_BLOCKS) convert x -> g_Xh (fp16);
//             blocks [CONV_BLOCKS, CONV_BLOCKS+DEQ_BLOCKS) dequant W -> g_Wh.
__global__ void prep_kernel(const float4* __restrict__ x,
                            const int* __restrict__ Wq, const float* __restrict__ scales,
                            const float* __restrict__ zeros, const void* __restrict__ mask,
                            const float* __restrict__ scale2) {
    if (blockIdx.x < CONV_BLOCKS) {
        // ---- convert x ----
        size_t i = (size_t)blockIdx.x * blockDim.x + threadIdx.x;
        float4 a = x[i * 2 + 0];
        float4 b = x[i * 2 + 1];
        unsigned short h[8];
        h[0] = __half_as_ushort(__float2half_rn(a.x)); h[1] = __half_as_ushort(__float2half_rn(a.y));
        h[2] = __half_as_ushort(__float2half_rn(a.z)); h[3] = __half_as_ushort(__float2half_rn(a.w));
        h[4] = __half_as_ushort(__float2half_rn(b.x)); h[5] = __half_as_ushort(__float2half_rn(b.y));
        h[6] = __half_as_ushort(__float2half_rn(b.z)); h[7] = __half_as_ushort(__float2half_rn(b.w));
        uint4 v;
        v.x = (uint32_t)h[0] | ((uint32_t)h[1] << 16);
        v.y = (uint32_t)h[2] | ((uint32_t)h[3] << 16);
        v.z = (uint32_t)h[4] | ((uint32_t)h[5] << 16);
        v.w = (uint32_t)h[6] | ((uint32_t)h[7] << 16);
        ((uint4*)g_Xh)[i] = v;
    } else {
        // ---- dequant W ----
        size_t t = (size_t)(blockIdx.x - CONV_BLOCKS) * blockDim.x + threadIdx.x;
        size_t base = t * 8;
        int row = (int)(base >> 12);
        int col = (int)(base & 4095);
        float s = scales[row];
        float z = zeros[row];
        int4 q0 = *(const int4*)(Wq + base);
        int4 q1 = *(const int4*)(Wq + base + 4);
        float4 c0 = *(const float4*)(scale2 + col);
        float4 c1 = *(const float4*)(scale2 + col + 4);
        float mv[8];
        int mode = g_mask_mode;
        if (mode == 0) {
            uint2 mb = *(const uint2*)((const unsigned char*)mask + base);
            mv[0] = (mb.x & 0x000000FFu) ? 1.f : 0.f;
            mv[1] = (mb.x & 0x0000FF00u) ? 1.f : 0.f;
            mv[2] = (mb.x & 0x00FF0000u) ? 1.f : 0.f;
            mv[3] = (mb.x & 0xFF000000u) ? 1.f : 0.f;
            mv[4] = (mb.y & 0x000000FFu) ? 1.f : 0.f;
            mv[5] = (mb.y & 0x0000FF00u) ? 1.f : 0.f;
            mv[6] = (mb.y & 0x00FF0000u) ? 1.f : 0.f;
            mv[7] = (mb.y & 0xFF000000u) ? 1.f : 0.f;
        } else if (mode == 1) {
            int4 m0 = *(const int4*)((const int*)mask + base);
            int4 m1 = *(const int4*)((const int*)mask + base + 4);
            mv[0] = m0.x ? 1.f : 0.f; mv[1] = m0.y ? 1.f : 0.f;
            mv[2] = m0.z ? 1.f : 0.f; mv[3] = m0.w ? 1.f : 0.f;
            mv[4] = m1.x ? 1.f : 0.f; mv[5] = m1.y ? 1.f : 0.f;
            mv[6] = m1.z ? 1.f : 0.f; mv[7] = m1.w ? 1.f : 0.f;
        } else {
            float4 m0 = *(const float4*)((const float*)mask + base);
            float4 m1 = *(const float4*)((const float*)mask + base + 4);
            mv[0] = m0.x; mv[1] = m0.y; mv[2] = m0.z; mv[3] = m0.w;
            mv[4] = m1.x; mv[5] = m1.y; mv[6] = m1.z; mv[7] = m1.w;
        }
        float qf[8] = {(float)q0.x, (float)q0.y, (float)q0.z, (float)q0.w,
                       (float)q1.x, (float)q1.y, (float)q1.z, (float)q1.w};
        float cf[8] = {c0.x, c0.y, c0.z, c0.w, c1.x, c1.y, c1.z, c1.w};
        unsigned short h[8];
#pragma unroll
        for (int i = 0; i < 8; i++)
            h[i] = __half_as_ushort(__float2half_rn((qf[i] - z) * s * cf[i] * mv[i]));
        uint4 v;
        v.x = (uint32_t)h[0] | ((uint32_t)h[1] << 16);
        v.y = (uint32_t)h[2] | ((uint32_t)h[3] << 16);
        v.z = (uint32_t)h[4] | ((uint32_t)h[5] << 16);
        v.w = (uint32_t)h[6] | ((uint32_t)h[7] << 16);
        *(uint4*)(g_Wh + base) = v;
    }
}

// ---------------------------------------------------------------------------
// GEMM: 256x128x64 block tile, 256 threads (8 warps, 4m x 2n), warp tile 64x64,
// register double-buffered fragments, 4-stage cp.async, 1 CTA/SM.
// smem rows: 64 halves padded to 72 (144 B) => conflict-free ldmatrix.
// ---------------------------------------------------------------------------
static constexpr int BM = 256, BN = 128, BK = 64, STAGES = 4;
static constexpr int KITER = INF / BK;                 // 64
static constexpr int ROWB = 144;                       // padded row bytes (72 halves)
static constexpr int A_BYTES = BM * ROWB;              // 36864
static constexpr int B_BYTES = BN * ROWB;              // 18432
static constexpr int STAGE_BYTES = A_BYTES + B_BYTES;  // 55296
static constexpr int SMEM_CTRL = 512;                  // bias tile (128 f32)
static constexpr int SMEM_TOTAL = SMEM_CTRL + STAGES * STAGE_BYTES;  // 221696

__device__ __forceinline__ uint32_t smem_u32(const void* p) {
    uint32_t a;
    asm("{ .reg .u64 t; cvta.to.shared.u64 t, %1; cvt.u32.u64 %0, t; }" : "=r"(a) : "l"(p));
    return a;
}

__device__ __forceinline__ void cp_async16(uint32_t sdst, const void* gsrc) {
    asm volatile("cp.async.cg.shared.global [%0], [%1], 16;" :: "r"(sdst), "l"(gsrc) : "memory");
}

__device__ __forceinline__ void ldmatrix_x4(uint32_t& r0, uint32_t& r1, uint32_t& r2, uint32_t& r3,
                                            uint32_t addr) {
    asm volatile("ldmatrix.sync.aligned.m8n8.x4.shared.b16 {%0,%1,%2,%3}, [%4];"
                 : "=r"(r0), "=r"(r1), "=r"(r2), "=r"(r3) : "r"(addr));
}

__device__ __forceinline__ void mma16816(float* c, uint32_t a0, uint32_t a1, uint32_t a2,
                                         uint32_t a3, uint32_t b0, uint32_t b1) {
    asm volatile(
        "mma.sync.aligned.m16n8k16.row.col.f32.f16.f16.f32 "
        "{%0,%1,%2,%3}, {%4,%5,%6,%7}, {%8,%9}, {%0,%1,%2,%3};"
        : "+f"(c[0]), "+f"(c[1]), "+f"(c[2]), "+f"(c[3])
        : "r"(a0), "r"(a1), "r"(a2), "r"(a3), "r"(b0), "r"(b1));
}

// full-burst stage load: A 256x8 chunks (8/thr), B 128x8 (4/thr)
__device__ __forceinline__ void load_stage(uint32_t sb, int buf, const __half* Ag, const __half* Bg,
                                           int k0, int tid) {
    uint32_t sA = sb + SMEM_CTRL + buf * STAGE_BYTES;
    uint32_t sB = sA + A_BYTES;
    const __half* Ak = Ag + k0;
    const __half* Bk = Bg + k0;
#pragma unroll
    for (int i = 0; i < 8; i++) {          // A: 256 rows x 8 16B-chunks = 2048 / 256 thr
        int ch = tid + (i << 8);
        int r = ch >> 3, c = ch & 7;
        cp_async16(sA + (uint32_t)r * ROWB + (uint32_t)(c << 4), Ak + (size_t)r * INF + (c << 3));
    }
#pragma unroll
    for (int i = 0; i < 4; i++) {          // B: 128 rows x 8 chunks = 1024 / 256 thr
        int ch = tid + (i << 8);
        int r = ch >> 3, c = ch & 7;
        cp_async16(sB + (uint32_t)r * ROWB + (uint32_t)(c << 4), Bk + (size_t)r * INF + (c << 3));
    }
}

// fragment prefetch: A 4 x4 (m64 x k16), B 4 x4 (n64 x k16)
__device__ __forceinline__ void ld_frags(uint32_t (&fa)[4][4], uint32_t (&fb)[4][4],
                                         uint32_t sA, uint32_t sB,
                                         uint32_t a_off, uint32_t b_off, uint32_t kb) {
#pragma unroll
    for (int mt = 0; mt < 4; mt++)
        ldmatrix_x4(fa[mt][0], fa[mt][1], fa[mt][2], fa[mt][3],
                    sA + a_off + (uint32_t)mt * 16 * ROWB + kb);
#pragma unroll
    for (int g = 0; g < 4; g++)
        ldmatrix_x4(fb[g][0], fb[g][1], fb[g][2], fb[g][3],
                    sB + b_off + (uint32_t)g * 16 * ROWB + kb);
}

__device__ __forceinline__ void compute_frags(float (&acc)[4][8][4],
                                              const uint32_t (&fa)[4][4],
                                              const uint32_t (&fb)[4][4]) {
#pragma unroll
    for (int mt = 0; mt < 4; mt++)
#pragma unroll
        for (int g = 0; g < 4; g++) {
            mma16816(acc[mt][g * 2 + 0], fa[mt][0], fa[mt][1], fa[mt][2], fa[mt][3],
                     fb[g][0], fb[g][1]);
            mma16816(acc[mt][g * 2 + 1], fa[mt][0], fa[mt][1], fa[mt][2], fa[mt][3],
                     fb[g][2], fb[g][3]);
        }
}

__global__ void __launch_bounds__(256, 1)
gemm_f16_kernel(const float* __restrict__ bias, float* __restrict__ out) {
    extern __shared__ char smem[];
    const uint32_t sb = smem_u32(smem);
    const int tid = threadIdx.x, wid = tid >> 5, lid = tid & 31;
    const int wm = wid & 3, wn = wid >> 2;           // warp grid 4m x 2n
    const int tile_n = blockIdx.x & 31;              // n-fast raster (B reuse in L2)
    const int tile_m = blockIdx.x >> 5;              // 32 m-tiles

    // stage bias tile (128 floats for this n-tile)
    if (tid < 128) ((float*)smem)[tid] = bias[tile_n * BN + tid];

    const __half* Ag = g_Xh + (size_t)tile_m * BM * INF;
    const __half* Bg = g_Wh + (size_t)tile_n * BN * INF;

    // ldmatrix per-lane base offsets (within a stage's tiles)
    const uint32_t a_off = (uint32_t)(wm * 64 + (lid & 15)) * ROWB + (uint32_t)(lid >> 4) * 16;
    const uint32_t b_off = (uint32_t)(wn * 64 + ((lid >> 4) << 3) + (lid & 7)) * ROWB
                         + (uint32_t)((lid >> 3) & 1) * 16;

    float acc[4][8][4];
#pragma unroll
    for (int mt = 0; mt < 4; mt++)
#pragma unroll
        for (int nt = 0; nt < 8; nt++)
#pragma unroll
            for (int j = 0; j < 4; j++) acc[mt][nt][j] = 0.f;

    // prologue: load stages 0,1,2
    load_stage(sb, 0, Ag, Bg, 0, tid);
    asm volatile("cp.async.commit_group;" ::: "memory");
    load_stage(sb, 1, Ag, Bg, BK, tid);
    asm volatile("cp.async.commit_group;" ::: "memory");
    load_stage(sb, 2, Ag, Bg, 2 * BK, tid);
    asm volatile("cp.async.commit_group;" ::: "memory");
    asm volatile("cp.async.wait_group 2;" ::: "memory");
    __syncthreads();

    uint32_t fa0[4][4], fb0[4][4], fa1[4][4], fb1[4][4];
    // preload step-0 fragments from stage 0
    ld_frags(fa0, fb0, sb + SMEM_CTRL, sb + SMEM_CTRL + A_BYTES, a_off, b_off, 0);

    int buf = 0;                 // stage buffer for iter s
    int lbuf = 3;                // stage buffer for iter s+3 loads
    for (int s = 0; s < KITER; s++) {
        const uint32_t sA = sb + SMEM_CTRL + buf * STAGE_BYTES;
        const uint32_t sBt = sA + A_BYTES;

        // step 0: prefetch frags k16#1; issue loads for stage s+3; compute k16#0
        ld_frags(fa1, fb1, sA, sBt, a_off, b_off, 32);
        int ns = s + STAGES - 1;
        if (ns < KITER) load_stage(sb, lbuf, Ag, Bg, ns * BK, tid);
        asm volatile("cp.async.commit_group;" ::: "memory");
        compute_frags(acc, fa0, fb0);

        // step 1: prefetch k16#2; compute k16#1
        ld_frags(fa0, fb0, sA, sBt, a_off, b_off, 64);
        compute_frags(acc, fa1, fb1);

        // step 2: prefetch k16#3; compute k16#2
        ld_frags(fa1, fb1, sA, sBt, a_off, b_off, 96);
        compute_frags(acc, fa0, fb0);

        // step 3: stage s+1 ready (2 groups may remain outstanding);
        //         prefetch its k16#0; compute k16#3
        asm volatile("cp.async.wait_group 2;" ::: "memory");
        __syncthreads();
        buf = (buf + 1) & 3;
        lbuf = (lbuf + 1) & 3;
        if (s + 1 < KITER) {
            const uint32_t nA = sb + SMEM_CTRL + buf * STAGE_BYTES;
            ld_frags(fa0, fb0, nA, nA + A_BYTES, a_off, b_off, 0);
        }
        compute_frags(acc, fa1, fb1);
    }

    // epilogue: fragment c -> global (+bias)
    const float* bsm = (const float*)smem;
    float* outbase = out + (size_t)(tile_m * BM + wm * 64) * OUTF + tile_n * BN;
    const int rl = lid >> 2;
    const int cl = (lid & 3) * 2;
#pragma unroll
    for (int mt = 0; mt < 4; mt++) {
#pragma unroll
        for (int nt = 0; nt < 8; nt++) {
            int c = wn * 64 + nt * 8 + cl;
            float b0v = bsm[c], b1v = bsm[c + 1];
            int r = mt * 16 + rl;
            float2 v0 = make_float2(acc[mt][nt][0] + b0v, acc[mt][nt][1] + b1v);
            *(float2*)(outbase + (size_t)r * OUTF + c) = v0;
            float2 v1 = make_float2(acc[mt][nt][2] + b0v, acc[mt][nt][3] + b1v);
            *(float2*)(outbase + (size_t)(r + 8) * OUTF + c) = v1;
        }
    }
}

// ---------------------------------------------------------------------------
extern "C" void kernel_launch(void* const* d_in, const int* in_sizes, int n_in,
                              void* d_out, int out_size) {
    const float* x      = (const float*)d_in[0];
    const int*   Wq     = (const int*)d_in[1];
    const float* scales = (const float*)d_in[2];
    const float* zeros  = (const float*)d_in[3];
    const void*  mask   = d_in[4];
    const float* scale2 = (const float*)d_in[5];
    const float* bias   = (const float*)d_in[6];
    float*       out    = (float*)d_out;

    cudaFuncSetAttribute(gemm_f16_kernel, cudaFuncAttributeMaxDynamicSharedMemorySize, SMEM_TOTAL);

    detect_mask_kernel<<<1, 256>>>((const unsigned int*)mask);
    prep_kernel<<<CONV_BLOCKS + DEQ_BLOCKS, 256>>>((const float4*)x, Wq, scales, zeros,
                                                   mask, scale2);
    gemm_f16_kernel<<<(TOKS / BM) * (OUTF / BN), 256, SMEM_TOTAL>>>(bias, out);
}

// round 17
// speedup vs baseline: 1.0048x; 1.0031x over previous
#include <cuda_runtime.h>
#include <cuda_fp16.h>
#include <cstdint>

// ---------------------------------------------------------------------------
// out[8192,4096] = x[8192,4096] @ W^T + bias
//   W = (W_q - zeros) * scales * scale2 * mask   (static per launch)
//
// Classic tensor-core path (base PTX on this toolchain):
// mma.sync.m16n8k16 (HMMA) + cp.async (LDGSTS) + ldmatrix (LDSM).
// R17 = R14 (best measured: detect_mask + fused prep + 256x128x64 GEMM,
// 8 warps 4m x 2n, 64x64 warp tiles, reg double-buffered frags, 4-stage
// cp.async, 1 CTA/SM) + ONE micro-change: epilogue stores use st.global.cs
// (cache-streaming) so the 128 MB write-once output doesn't evict A/B panels
// from L2 while co-resident CTAs' cp.asyncs still need them.
// ---------------------------------------------------------------------------

#define TOKS 8192
#define INF  4096
#define OUTF 4096

__device__ __align__(256) __half g_Xh[(size_t)TOKS * INF];   // 64 MB A (row-major, K contig)
__device__ __align__(256) __half g_Wh[(size_t)OUTF * INF];   // 32 MB B ([n][k], K contig)
__device__ int g_mask_mode;   // 0 = int8, 1 = int32, 2 = float32

// ---------------------------------------------------------------------------
// Aux kernels
// ---------------------------------------------------------------------------
__global__ void detect_mask_kernel(const unsigned int* __restrict__ m) {
    __shared__ int s_f32, s_gt1;
    if (threadIdx.x == 0) { s_f32 = 0; s_gt1 = 0; }
    __syncthreads();
    int f32 = 0, gt1 = 0;
#pragma unroll
    for (int i = 0; i < 8; i++) {
        unsigned v = m[threadIdx.x * 8 + i];
        f32 |= (v == 0x3F800000u);
        gt1 |= (v > 1u);
    }
    if (f32) atomicOr(&s_f32, 1);
    if (gt1) atomicOr(&s_gt1, 1);
    __syncthreads();
    if (threadIdx.x == 0)
        g_mask_mode = s_f32 ? 2 : (s_gt1 ? 0 : 1);
}

static constexpr int CONV_BLOCKS = 16384;   // x convert: 16384*256 threads x 8 elems
static constexpr int DEQ_BLOCKS  = 8192;    // W dequant:  8192*256 threads x 8 elems

// Fused prep: blocks [0, CONV_BLOCKS) convert x -> g_Xh (fp16);
//             blocks [CONV_BLOCKS, CONV_BLOCKS+DEQ_BLOCKS) dequant W -> g_Wh.
__global__ void prep_kernel(const float4* __restrict__ x,
                            const int* __restrict__ Wq, const float* __restrict__ scales,
                            const float* __restrict__ zeros, const void* __restrict__ mask,
                            const float* __restrict__ scale2) {
    if (blockIdx.x < CONV_BLOCKS) {
        // ---- convert x ----
        size_t i = (size_t)blockIdx.x * blockDim.x + threadIdx.x;
        float4 a = x[i * 2 + 0];
        float4 b = x[i * 2 + 1];
        unsigned short h[8];
        h[0] = __half_as_ushort(__float2half_rn(a.x)); h[1] = __half_as_ushort(__float2half_rn(a.y));
        h[2] = __half_as_ushort(__float2half_rn(a.z)); h[3] = __half_as_ushort(__float2half_rn(a.w));
        h[4] = __half_as_ushort(__float2half_rn(b.x)); h[5] = __half_as_ushort(__float2half_rn(b.y));
        h[6] = __half_as_ushort(__float2half_rn(b.z)); h[7] = __half_as_ushort(__float2half_rn(b.w));
        uint4 v;
        v.x = (uint32_t)h[0] | ((uint32_t)h[1] << 16);
        v.y = (uint32_t)h[2] | ((uint32_t)h[3] << 16);
        v.z = (uint32_t)h[4] | ((uint32_t)h[5] << 16);
        v.w = (uint32_t)h[6] | ((uint32_t)h[7] << 16);
        ((uint4*)g_Xh)[i] = v;
    } else {
        // ---- dequant W ----
        size_t t = (size_t)(blockIdx.x - CONV_BLOCKS) * blockDim.x + threadIdx.x;
        size_t base = t * 8;
        int row = (int)(base >> 12);
        int col = (int)(base & 4095);
        float s = scales[row];
        float z = zeros[row];
        int4 q0 = *(const int4*)(Wq + base);
        int4 q1 = *(const int4*)(Wq + base + 4);
        float4 c0 = *(const float4*)(scale2 + col);
        float4 c1 = *(const float4*)(scale2 + col + 4);
        float mv[8];
        int mode = g_mask_mode;
        if (mode == 0) {
            uint2 mb = *(const uint2*)((const unsigned char*)mask + base);
            mv[0] = (mb.x & 0x000000FFu) ? 1.f : 0.f;
            mv[1] = (mb.x & 0x0000FF00u) ? 1.f : 0.f;
            mv[2] = (mb.x & 0x00FF0000u) ? 1.f : 0.f;
            mv[3] = (mb.x & 0xFF000000u) ? 1.f : 0.f;
            mv[4] = (mb.y & 0x000000FFu) ? 1.f : 0.f;
            mv[5] = (mb.y & 0x0000FF00u) ? 1.f : 0.f;
            mv[6] = (mb.y & 0x00FF0000u) ? 1.f : 0.f;
            mv[7] = (mb.y & 0xFF000000u) ? 1.f : 0.f;
        } else if (mode == 1) {
            int4 m0 = *(const int4*)((const int*)mask + base);
            int4 m1 = *(const int4*)((const int*)mask + base + 4);
            mv[0] = m0.x ? 1.f : 0.f; mv[1] = m0.y ? 1.f : 0.f;
            mv[2] = m0.z ? 1.f : 0.f; mv[3] = m0.w ? 1.f : 0.f;
            mv[4] = m1.x ? 1.f : 0.f; mv[5] = m1.y ? 1.f : 0.f;
            mv[6] = m1.z ? 1.f : 0.f; mv[7] = m1.w ? 1.f : 0.f;
        } else {
            float4 m0 = *(const float4*)((const float*)mask + base);
            float4 m1 = *(const float4*)((const float*)mask + base + 4);
            mv[0] = m0.x; mv[1] = m0.y; mv[2] = m0.z; mv[3] = m0.w;
            mv[4] = m1.x; mv[5] = m1.y; mv[6] = m1.z; mv[7] = m1.w;
        }
        float qf[8] = {(float)q0.x, (float)q0.y, (float)q0.z, (float)q0.w,
                       (float)q1.x, (float)q1.y, (float)q1.z, (float)q1.w};
        float cf[8] = {c0.x, c0.y, c0.z, c0.w, c1.x, c1.y, c1.z, c1.w};
        unsigned short h[8];
#pragma unroll
        for (int i = 0; i < 8; i++)
            h[i] = __half_as_ushort(__float2half_rn((qf[i] - z) * s * cf[i] * mv[i]));
        uint4 v;
        v.x = (uint32_t)h[0] | ((uint32_t)h[1] << 16);
        v.y = (uint32_t)h[2] | ((uint32_t)h[3] << 16);
        v.z = (uint32_t)h[4] | ((uint32_t)h[5] << 16);
        v.w = (uint32_t)h[6] | ((uint32_t)h[7] << 16);
        *(uint4*)(g_Wh + base) = v;
    }
}

// ---------------------------------------------------------------------------
// GEMM: 256x128x64 block tile, 256 threads (8 warps, 4m x 2n), warp tile 64x64,
// register double-buffered fragments, 4-stage cp.async, 1 CTA/SM.
// smem rows: 64 halves padded to 72 (144 B) => conflict-free ldmatrix.
// ---------------------------------------------------------------------------
static constexpr int BM = 256, BN = 128, BK = 64, STAGES = 4;
static constexpr int KITER = INF / BK;                 // 64
static constexpr int ROWB = 144;                       // padded row bytes (72 halves)
static constexpr int A_BYTES = BM * ROWB;              // 36864
static constexpr int B_BYTES = BN * ROWB;              // 18432
static constexpr int STAGE_BYTES = A_BYTES + B_BYTES;  // 55296
static constexpr int SMEM_CTRL = 512;                  // bias tile (128 f32)
static constexpr int SMEM_TOTAL = SMEM_CTRL + STAGES * STAGE_BYTES;  // 221696

__device__ __forceinline__ uint32_t smem_u32(const void* p) {
    uint32_t a;
    asm("{ .reg .u64 t; cvta.to.shared.u64 t, %1; cvt.u32.u64 %0, t; }" : "=r"(a) : "l"(p));
    return a;
}

__device__ __forceinline__ void cp_async16(uint32_t sdst, const void* gsrc) {
    asm volatile("cp.async.cg.shared.global [%0], [%1], 16;" :: "r"(sdst), "l"(gsrc) : "memory");
}

__device__ __forceinline__ void ldmatrix_x4(uint32_t& r0, uint32_t& r1, uint32_t& r2, uint32_t& r3,
                                            uint32_t addr) {
    asm volatile("ldmatrix.sync.aligned.m8n8.x4.shared.b16 {%0,%1,%2,%3}, [%4];"
                 : "=r"(r0), "=r"(r1), "=r"(r2), "=r"(r3) : "r"(addr));
}

__device__ __forceinline__ void mma16816(float* c, uint32_t a0, uint32_t a1, uint32_t a2,
                                         uint32_t a3, uint32_t b0, uint32_t b1) {
    asm volatile(
        "mma.sync.aligned.m16n8k16.row.col.f32.f16.f16.f32 "
        "{%0,%1,%2,%3}, {%4,%5,%6,%7}, {%8,%9}, {%0,%1,%2,%3};"
        : "+f"(c[0]), "+f"(c[1]), "+f"(c[2]), "+f"(c[3])
        : "r"(a0), "r"(a1), "r"(a2), "r"(a3), "r"(b0), "r"(b1));
}

// cache-streaming v2 store: output is write-once, never re-read -> evict-first
__device__ __forceinline__ void stg_cs_v2(float* p, float v0, float v1) {
    asm volatile("st.global.cs.v2.f32 [%0], {%1, %2};" :: "l"(p), "f"(v0), "f"(v1) : "memory");
}

// full-burst stage load: A 256x8 chunks (8/thr), B 128x8 (4/thr)
__device__ __forceinline__ void load_stage(uint32_t sb, int buf, const __half* Ag, const __half* Bg,
                                           int k0, int tid) {
    uint32_t sA = sb + SMEM_CTRL + buf * STAGE_BYTES;
    uint32_t sB = sA + A_BYTES;
    const __half* Ak = Ag + k0;
    const __half* Bk = Bg + k0;
#pragma unroll
    for (int i = 0; i < 8; i++) {          // A: 256 rows x 8 16B-chunks = 2048 / 256 thr
        int ch = tid + (i << 8);
        int r = ch >> 3, c = ch & 7;
        cp_async16(sA + (uint32_t)r * ROWB + (uint32_t)(c << 4), Ak + (size_t)r * INF + (c << 3));
    }
#pragma unroll
    for (int i = 0; i < 4; i++) {          // B: 128 rows x 8 chunks = 1024 / 256 thr
        int ch = tid + (i << 8);
        int r = ch >> 3, c = ch & 7;
        cp_async16(sB + (uint32_t)r * ROWB + (uint32_t)(c << 4), Bk + (size_t)r * INF + (c << 3));
    }
}

// fragment prefetch: A 4 x4 (m64 x k16), B 4 x4 (n64 x k16)
__device__ __forceinline__ void ld_frags(uint32_t (&fa)[4][4], uint32_t (&fb)[4][4],
                                         uint32_t sA, uint32_t sB,
                                         uint32_t a_off, uint32_t b_off, uint32_t kb) {
#pragma unroll
    for (int mt = 0; mt < 4; mt++)
        ldmatrix_x4(fa[mt][0], fa[mt][1], fa[mt][2], fa[mt][3],
                    sA + a_off + (uint32_t)mt * 16 * ROWB + kb);
#pragma unroll
    for (int g = 0; g < 4; g++)
        ldmatrix_x4(fb[g][0], fb[g][1], fb[g][2], fb[g][3],
                    sB + b_off + (uint32_t)g * 16 * ROWB + kb);
}

__device__ __forceinline__ void compute_frags(float (&acc)[4][8][4],
                                              const uint32_t (&fa)[4][4],
                                              const uint32_t (&fb)[4][4]) {
#pragma unroll
    for (int mt = 0; mt < 4; mt++)
#pragma unroll
        for (int g = 0; g < 4; g++) {
            mma16816(acc[mt][g * 2 + 0], fa[mt][0], fa[mt][1], fa[mt][2], fa[mt][3],
                     fb[g][0], fb[g][1]);
            mma16816(acc[mt][g * 2 + 1], fa[mt][0], fa[mt][1], fa[mt][2], fa[mt][3],
                     fb[g][2], fb[g][3]);
        }
}

__global__ void __launch_bounds__(256, 1)
gemm_f16_kernel(const float* __restrict__ bias, float* __restrict__ out) {
    extern __shared__ char smem[];
    const uint32_t sb = smem_u32(smem);
    const int tid = threadIdx.x, wid = tid >> 5, lid = tid & 31;
    const int wm = wid & 3, wn = wid >> 2;           // warp grid 4m x 2n
    const int tile_n = blockIdx.x & 31;              // n-fast raster (B reuse in L2)
    const int tile_m = blockIdx.x >> 5;              // 32 m-tiles

    // stage bias tile (128 floats for this n-tile)
    if (tid < 128) ((float*)smem)[tid] = bias[tile_n * BN + tid];

    const __half* Ag = g_Xh + (size_t)tile_m * BM * INF;
    const __half* Bg = g_Wh + (size_t)tile_n * BN * INF;

    // ldmatrix per-lane base offsets (within a stage's tiles)
    const uint32_t a_off = (uint32_t)(wm * 64 + (lid & 15)) * ROWB + (uint32_t)(lid >> 4) * 16;
    const uint32_t b_off = (uint32_t)(wn * 64 + ((lid >> 4) << 3) + (lid & 7)) * ROWB
                         + (uint32_t)((lid >> 3) & 1) * 16;

    float acc[4][8][4];
#pragma unroll
    for (int mt = 0; mt < 4; mt++)
#pragma unroll
        for (int nt = 0; nt < 8; nt++)
#pragma unroll
            for (int j = 0; j < 4; j++) acc[mt][nt][j] = 0.f;

    // prologue: load stages 0,1,2
    load_stage(sb, 0, Ag, Bg, 0, tid);
    asm volatile("cp.async.commit_group;" ::: "memory");
    load_stage(sb, 1, Ag, Bg, BK, tid);
    asm volatile("cp.async.commit_group;" ::: "memory");
    load_stage(sb, 2, Ag, Bg, 2 * BK, tid);
    asm volatile("cp.async.commit_group;" ::: "memory");
    asm volatile("cp.async.wait_group 2;" ::: "memory");
    __syncthreads();

    uint32_t fa0[4][4], fb0[4][4], fa1[4][4], fb1[4][4];
    // preload step-0 fragments from stage 0
    ld_frags(fa0, fb0, sb + SMEM_CTRL, sb + SMEM_CTRL + A_BYTES, a_off, b_off, 0);

    int buf = 0;                 // stage buffer for iter s
    int lbuf = 3;                // stage buffer for iter s+3 loads
    for (int s = 0; s < KITER; s++) {
        const uint32_t sA = sb + SMEM_CTRL + buf * STAGE_BYTES;
        const uint32_t sBt = sA + A_BYTES;

        // step 0: prefetch frags k16#1; issue loads for stage s+3; compute k16#0
        ld_frags(fa1, fb1, sA, sBt, a_off, b_off, 32);
        int ns = s + STAGES - 1;
        if (ns < KITER) load_stage(sb, lbuf, Ag, Bg, ns * BK, tid);
        asm volatile("cp.async.commit_group;" ::: "memory");
        compute_frags(acc, fa0, fb0);

        // step 1: prefetch k16#2; compute k16#1
        ld_frags(fa0, fb0, sA, sBt, a_off, b_off, 64);
        compute_frags(acc, fa1, fb1);

        // step 2: prefetch k16#3; compute k16#2
        ld_frags(fa1, fb1, sA, sBt, a_off, b_off, 96);
        compute_frags(acc, fa0, fb0);

        // step 3: stage s+1 ready (2 groups may remain outstanding);
        //         prefetch its k16#0; compute k16#3
        asm volatile("cp.async.wait_group 2;" ::: "memory");
        __syncthreads();
        buf = (buf + 1) & 3;
        lbuf = (lbuf + 1) & 3;
        if (s + 1 < KITER) {
            const uint32_t nA = sb + SMEM_CTRL + buf * STAGE_BYTES;
            ld_frags(fa0, fb0, nA, nA + A_BYTES, a_off, b_off, 0);
        }
        compute_frags(acc, fa1, fb1);
    }

    // epilogue: fragment c -> global (+bias), cache-streaming stores
    const float* bsm = (const float*)smem;
    float* outbase = out + (size_t)(tile_m * BM + wm * 64) * OUTF + tile_n * BN;
    const int rl = lid >> 2;
    const int cl = (lid & 3) * 2;
#pragma unroll
    for (int mt = 0; mt < 4; mt++) {
#pragma unroll
        for (int nt = 0; nt < 8; nt++) {
            int c = wn * 64 + nt * 8 + cl;
            float b0v = bsm[c], b1v = bsm[c + 1];
            int r = mt * 16 + rl;
            stg_cs_v2(outbase + (size_t)r * OUTF + c,
                      acc[mt][nt][0] + b0v, acc[mt][nt][1] + b1v);
            stg_cs_v2(outbase + (size_t)(r + 8) * OUTF + c,
                      acc[mt][nt][2] + b0v, acc[mt][nt][3] + b1v);
        }
    }
}

// ---------------------------------------------------------------------------
extern "C" void kernel_launch(void* const* d_in, const int* in_sizes, int n_in,
                              void* d_out, int out_size) {
    const float* x      = (const float*)d_in[0];
    const int*   Wq     = (const int*)d_in[1];
    const float* scales = (const float*)d_in[2];
    const float* zeros  = (const float*)d_in[3];
    const void*  mask   = d_in[4];
    const float* scale2 = (const float*)d_in[5];
    const float* bias   = (const float*)d_in[6];
    float*       out    = (float*)d_out;

    cudaFuncSetAttribute(gemm_f16_kernel, cudaFuncAttributeMaxDynamicSharedMemorySize, SMEM_TOTAL);

    detect_mask_kernel<<<1, 256>>>((const unsigned int*)mask);
    prep_kernel<<<CONV_BLOCKS + DEQ_BLOCKS, 256>>>((const float4*)x, Wq, scales, zeros,
                                                   mask, scale2);
    gemm_f16_kernel<<<(TOKS / BM) * (OUTF / BN), 256, SMEM_TOTAL>>>(bias, out);
}